// round 1
// baseline (speedup 1.0000x reference)
#include <cuda_runtime.h>

#define N 1024
#define D 64
#define H 8
#define IDXE 64
#define NSPLIT 32     // spmm K-splits
#define KC 32         // m-chunk per block
#define NT 128        // n-tile for spmm
#define TG_SPLIT 8
#define PADN 132
#define PADU 68

// ---------------- static scratch ----------------
__device__ float g_a[N * N];
__device__ float g_ad[N * N];
__device__ float g_rowpb[2][N][H];   // row-proj + b1
__device__ float g_col[2][N][H];
__device__ float g_tgp[TG_SPLIT][N];
__device__ float g_xbuf[2][N * D];
__device__ float g_u[5][N * D];
__device__ float g_part[NSPLIT][N * D];

// ---------------- projections: row/col factors of the edge MLP ----------------
__global__ void proj_kernel(const float* __restrict__ idx_emb,
                            const float* __restrict__ W1,
                            const float* __restrict__ b1) {
    int id = blockIdx.x * blockDim.x + threadIdx.x;   // 32768 threads
    int h  = id & 7;
    int s  = (id >> 3) & 1;
    int rc = (id >> 4) & 1;
    int n  = id >> 5;
    const float* w = W1 + s * (H * 129) + h * 129 + 1 + rc * IDXE;
    const float* e = idx_emb + n * IDXE;
    float acc = 0.f;
#pragma unroll 16
    for (int k = 0; k < IDXE; k++) acc = fmaf(e[k], w[k], acc);
    if (rc == 0) g_rowpb[s][n][h] = acc + b1[s * H + h];
    else         g_col[s][n][h]   = acc;
}

// ---------------- tg partials: column means of t_grad ----------------
__global__ void tg_kernel(const float* __restrict__ t_grad) {
    int n = blockIdx.x * 256 + threadIdx.x;
    int s = blockIdx.y;
    const int R = N / TG_SPLIT;
    float acc = 0.f;
    for (int m = s * R; m < (s + 1) * R; m++) acc += t_grad[m * N + n];
    g_tgp[s][n] = acc;
}

// ---------------- edge MLPs: compute a and ad ----------------
__device__ __forceinline__ float mlp_eval(float aval, const float* __restrict__ wa,
                                          const float* __restrict__ rc,
                                          const float* __restrict__ W2,
                                          const float* __restrict__ b2,
                                          const float* __restrict__ W3, float b3v) {
    float h1[H];
#pragma unroll
    for (int h = 0; h < H; h++)
        h1[h] = fmaxf(fmaf(aval, wa[h], rc[h]), 0.f);
    float out = b3v;
#pragma unroll
    for (int k = 0; k < H; k++) {
        float t = b2[k];
#pragma unroll
        for (int h = 0; h < H; h++) t = fmaf(W2[k * H + h], h1[h], t);
        out = fmaf(W3[k], fmaxf(t, 0.f), out);
    }
    return out;
}

__global__ void msg_kernel(const float* __restrict__ adj,
                           const float* __restrict__ adjd,
                           const float* __restrict__ W1,
                           const float* __restrict__ W2,
                           const float* __restrict__ b2,
                           const float* __restrict__ W3,
                           const float* __restrict__ b3) {
    __shared__ float wa[2][H], W2s[2][H * H], b2s[2][H], W3s[2][H], b3s[2];
    __shared__ float rcn[2][8][H];     // rowpb for 8 local n
    __shared__ float ccm[2][32][H];    // col for 32 local m
    int tid = threadIdx.x;
    int mb = blockIdx.x * 32, nb = blockIdx.y * 8;

    if (tid < 16)  wa[tid >> 3][tid & 7]   = W1[(tid >> 3) * (H * 129) + (tid & 7) * 129];
    if (tid < 128) W2s[tid >> 6][tid & 63] = W2[tid];
    if (tid < 16)  b2s[tid >> 3][tid & 7]  = b2[tid];
    if (tid < 16)  W3s[tid >> 3][tid & 7]  = W3[tid];
    if (tid < 2)   b3s[tid] = b3[tid];
    if (tid < 128) {
        int s = tid >> 6, r = (tid >> 3) & 7, h = tid & 7;
        rcn[s][r][h] = g_rowpb[s][nb + r][h];
    }
    for (int i = tid; i < 512; i += 256) {
        int s = i >> 8, mm = (i >> 3) & 31, h = i & 7;
        ccm[s][mm][h] = g_col[s][mb + mm][h];
    }
    __syncthreads();

    int mloc = tid & 31, nloc = tid >> 5;
    int n = nb + nloc, m = mb + mloc;
    float av  = adj[n * N + m];
    float adv = adjd[n * N + m];

    {
        float rc[H];
#pragma unroll
        for (int h = 0; h < H; h++) rc[h] = rcn[0][nloc][h] + ccm[0][mloc][h];
        g_a[n * N + m] = mlp_eval(av, wa[0], rc, W2s[0], b2s[0], W3s[0], b3s[0]);
    }
    {
        float rc[H];
#pragma unroll
        for (int h = 0; h < H; h++) rc[h] = rcn[1][nloc][h] + ccm[1][mloc][h];
        g_ad[n * N + m] = mlp_eval(adv, wa[1], rc, W2s[1], b2s[1], W3s[1], b3s[1]);
    }
}

// ---------------- U_q = x @ W[l][q] ----------------
__global__ void uproj_kernel(const float* __restrict__ y,
                             const float* __restrict__ gnn_W, int layer) {
    __shared__ float Ws[64 * 64];
    __shared__ float xs[32][65];
    int tid = threadIdx.x;
    int q = blockIdx.y;
    int m0 = blockIdx.x * 32;
    const float* x = (layer == 0) ? y : g_xbuf[layer - 1];
    const float* W = gnn_W + (layer * 5 + q) * 4096;
    for (int i = tid; i < 4096; i += 256) Ws[i] = W[i];
    for (int i = tid; i < 2048; i += 256)
        xs[i >> 6][i & 63] = x[(m0 + (i >> 6)) * D + (i & 63)];
    __syncthreads();
    int d = tid & 63, mg = tid >> 6;
    float acc[8] = {0, 0, 0, 0, 0, 0, 0, 0};
    for (int k = 0; k < 64; k++) {
        float w = Ws[k * 64 + d];
#pragma unroll
        for (int r = 0; r < 8; r++) acc[r] = fmaf(xs[mg * 8 + r][k], w, acc[r]);
    }
#pragma unroll
    for (int r = 0; r < 8; r++)
        g_u[q][(m0 + mg * 8 + r) * D + d] = acc[r];
}

// ---------------- fused 4-way product (split-K partials) ----------------
__global__ void __launch_bounds__(256, 2) spmm_kernel() {
    extern __shared__ float sm[];
    float* a_ds = sm;                    // [KC][PADN]  a[n,m] stored [m][n]
    float* a_ts = a_ds + KC * PADN;      // [KC][PADN]  a[m,n] stored [m][n]
    float* d_ds = a_ts + KC * PADN;
    float* d_ts = d_ds + KC * PADN;
    float* u0s  = d_ts + KC * PADN;      // [KC][PADU]
    float* u1s  = u0s + KC * PADU;
    float* u2s  = u1s + KC * PADU;
    float* u3s  = u2s + KC * PADU;

    int tid = threadIdx.x;
    int n0 = blockIdx.x * NT;
    int m0 = blockIdx.y * KC;

    // direct tiles: read a[(n0+i), m0+j] coalesced along j, store transposed
    for (int idx = tid; idx < NT * KC; idx += 256) {
        int i = idx >> 5, j = idx & 31;
        a_ds[j * PADN + i] = g_a[(n0 + i) * N + m0 + j];
        d_ds[j * PADN + i] = g_ad[(n0 + i) * N + m0 + j];
    }
    // transposed-use tiles: read a[(m0+j), n0+i] coalesced along i, store direct
    for (int idx = tid; idx < NT * KC; idx += 256) {
        int j = idx >> 7, i = idx & 127;
        a_ts[j * PADN + i] = g_a[(m0 + j) * N + n0 + i];
        d_ts[j * PADN + i] = g_ad[(m0 + j) * N + n0 + i];
    }
    for (int idx = tid; idx < KC * D; idx += 256) {
        int j = idx >> 6, d = idx & 63;
        u0s[j * PADU + d] = g_u[0][(m0 + j) * D + d];
        u1s[j * PADU + d] = g_u[1][(m0 + j) * D + d];
        u2s[j * PADU + d] = g_u[2][(m0 + j) * D + d];
        u3s[j * PADU + d] = g_u[3][(m0 + j) * D + d];
    }
    __syncthreads();

    int td = tid & 15, tn = tid >> 4;
    int dd = td * 4, nn = tn * 8;

    float acc[8][4];
#pragma unroll
    for (int i = 0; i < 8; i++)
#pragma unroll
        for (int c = 0; c < 4; c++) acc[i][c] = 0.f;

#pragma unroll 2
    for (int j = 0; j < KC; j++) {
        float4 u0 = *(const float4*)(u0s + j * PADU + dd);
        float4 u1 = *(const float4*)(u1s + j * PADU + dd);
        float4 u2 = *(const float4*)(u2s + j * PADU + dd);
        float4 u3 = *(const float4*)(u3s + j * PADU + dd);
        float aD[8], aT[8], bD[8], bT[8];
        *(float4*)(aD)     = *(const float4*)(a_ds + j * PADN + nn);
        *(float4*)(aD + 4) = *(const float4*)(a_ds + j * PADN + nn + 4);
        *(float4*)(aT)     = *(const float4*)(a_ts + j * PADN + nn);
        *(float4*)(aT + 4) = *(const float4*)(a_ts + j * PADN + nn + 4);
        *(float4*)(bD)     = *(const float4*)(d_ds + j * PADN + nn);
        *(float4*)(bD + 4) = *(const float4*)(d_ds + j * PADN + nn + 4);
        *(float4*)(bT)     = *(const float4*)(d_ts + j * PADN + nn);
        *(float4*)(bT + 4) = *(const float4*)(d_ts + j * PADN + nn + 4);
#pragma unroll
        for (int i = 0; i < 8; i++) {
            acc[i][0] = fmaf(aD[i], u0.x, fmaf(aT[i], u1.x, fmaf(bD[i], u2.x, fmaf(bT[i], u3.x, acc[i][0]))));
            acc[i][1] = fmaf(aD[i], u0.y, fmaf(aT[i], u1.y, fmaf(bD[i], u2.y, fmaf(bT[i], u3.y, acc[i][1]))));
            acc[i][2] = fmaf(aD[i], u0.z, fmaf(aT[i], u1.z, fmaf(bD[i], u2.z, fmaf(bT[i], u3.z, acc[i][2]))));
            acc[i][3] = fmaf(aD[i], u0.w, fmaf(aT[i], u1.w, fmaf(bD[i], u2.w, fmaf(bT[i], u3.w, acc[i][3]))));
        }
    }

    float* outp = g_part[blockIdx.y];
#pragma unroll
    for (int i = 0; i < 8; i++) {
        float4 v = make_float4(acc[i][0], acc[i][1], acc[i][2], acc[i][3]);
        *(float4*)(outp + (n0 + nn + i) * D + dd) = v;
    }
}

// ---------------- reduce split-K + bias (+relu) ----------------
__global__ void reduce_kernel(const float* __restrict__ gnn_b, int layer) {
    int id = blockIdx.x * 256 + threadIdx.x;   // N*D
    int d = id & 63;
    float acc = g_u[4][id] + gnn_b[layer * D + d];
#pragma unroll
    for (int s = 0; s < NSPLIT; s++) acc += g_part[s][id];
    g_xbuf[layer][id] = fmaxf(acc, 0.f);
}

// ---------------- final layer: no relu, scale by tg ----------------
__global__ void final_kernel(float* __restrict__ out, const float* __restrict__ gnn_b) {
    int id = blockIdx.x * 256 + threadIdx.x;
    int d = id & 63;
    int n = id >> 6;
    float acc = g_u[4][id] + gnn_b[2 * D + d];
#pragma unroll
    for (int s = 0; s < NSPLIT; s++) acc += g_part[s][id];
    float tg = 0.f;
#pragma unroll
    for (int s = 0; s < TG_SPLIT; s++) tg += g_tgp[s][n];
    out[id] = acc * tg * (1.0f / N);
}

// ---------------- launch ----------------
extern "C" void kernel_launch(void* const* d_in, const int* in_sizes, int n_in,
                              void* d_out, int out_size) {
    const float* y       = (const float*)d_in[0];
    const float* adj     = (const float*)d_in[1];
    const float* adjd    = (const float*)d_in[2];
    const float* t_grad  = (const float*)d_in[3];
    const float* idx_emb = (const float*)d_in[4];
    const float* msg_W1  = (const float*)d_in[5];
    const float* msg_b1  = (const float*)d_in[6];
    const float* msg_W2  = (const float*)d_in[7];
    const float* msg_b2  = (const float*)d_in[8];
    const float* msg_W3  = (const float*)d_in[9];
    const float* msg_b3  = (const float*)d_in[10];
    const float* gnn_W   = (const float*)d_in[11];
    const float* gnn_b   = (const float*)d_in[12];
    float* out = (float*)d_out;

    const int spmm_smem = (4 * KC * PADN + 4 * KC * PADU) * (int)sizeof(float); // 102400
    cudaFuncSetAttribute(spmm_kernel, cudaFuncAttributeMaxDynamicSharedMemorySize, spmm_smem);

    proj_kernel<<<128, 256>>>(idx_emb, msg_W1, msg_b1);
    tg_kernel<<<dim3(4, TG_SPLIT), 256>>>(t_grad);
    msg_kernel<<<dim3(32, 128), 256>>>(adj, adjd, msg_W1, msg_W2, msg_b2, msg_W3, msg_b3);

    for (int l = 0; l < 3; l++) {
        uproj_kernel<<<dim3(32, 5), 256>>>(y, gnn_W, l);
        spmm_kernel<<<dim3(N / NT, NSPLIT), 256, spmm_smem>>>();
        if (l < 2) reduce_kernel<<<256, 256>>>(gnn_b, l);
        else       final_kernel<<<256, 256>>>(out, gnn_b);
    }
}

// round 2
// speedup vs baseline: 1.0120x; 1.0120x over previous
#include <cuda_runtime.h>

#define N 1024
#define D 64
#define H 8
#define IDXE 64
#define NSPLIT 32     // spmm K-splits
#define KC 32         // m-chunk per block
#define NT 128        // n-tile for spmm
#define TG_SPLIT 8
#define PADN 132
#define PADU 68

// ---------------- static scratch ----------------
__device__ float g_a[N * N];
__device__ float g_ad[N * N];
__device__ float g_rowpb[2][N][H];   // row-proj + b1
__device__ float g_col[2][N][H];
__device__ float g_tgp[TG_SPLIT][N];
__device__ float g_xbuf[2][N * D];
__device__ float g_u[5][N * D];
__device__ float g_part[NSPLIT][N * D];

// ---------------- projections: row/col factors of the edge MLP ----------------
__global__ void proj_kernel(const float* __restrict__ idx_emb,
                            const float* __restrict__ W1,
                            const float* __restrict__ b1) {
    int id = blockIdx.x * blockDim.x + threadIdx.x;   // 32768 threads
    int h  = id & 7;
    int s  = (id >> 3) & 1;
    int rc = (id >> 4) & 1;
    int n  = id >> 5;
    const float* w = W1 + s * (H * 129) + h * 129 + 1 + rc * IDXE;
    const float* e = idx_emb + n * IDXE;
    float acc = 0.f;
#pragma unroll 16
    for (int k = 0; k < IDXE; k++) acc = fmaf(e[k], w[k], acc);
    if (rc == 0) g_rowpb[s][n][h] = acc + b1[s * H + h];
    else         g_col[s][n][h]   = acc;
}

// ---------------- tg partials: column means of t_grad ----------------
__global__ void tg_kernel(const float* __restrict__ t_grad) {
    int n = blockIdx.x * 256 + threadIdx.x;
    int s = blockIdx.y;
    const int R = N / TG_SPLIT;
    float acc = 0.f;
    for (int m = s * R; m < (s + 1) * R; m++) acc += t_grad[m * N + n];
    g_tgp[s][n] = acc;
}

// ---------------- edge MLPs: compute a and ad ----------------
__device__ __forceinline__ float mlp_eval(float aval, const float* __restrict__ wa,
                                          const float* __restrict__ rc,
                                          const float* __restrict__ W2,
                                          const float* __restrict__ b2,
                                          const float* __restrict__ W3, float b3v) {
    float h1[H];
#pragma unroll
    for (int h = 0; h < H; h++)
        h1[h] = fmaxf(fmaf(aval, wa[h], rc[h]), 0.f);
    float out = b3v;
#pragma unroll
    for (int k = 0; k < H; k++) {
        float t = b2[k];
#pragma unroll
        for (int h = 0; h < H; h++) t = fmaf(W2[k * H + h], h1[h], t);
        out = fmaf(W3[k], fmaxf(t, 0.f), out);
    }
    return out;
}

__global__ void msg_kernel(const float* __restrict__ adj,
                           const float* __restrict__ adjd,
                           const float* __restrict__ W1,
                           const float* __restrict__ W2,
                           const float* __restrict__ b2,
                           const float* __restrict__ W3,
                           const float* __restrict__ b3) {
    __shared__ float wa[2][H], W2s[2][H * H], b2s[2][H], W3s[2][H], b3s[2];
    __shared__ float rcn[2][8][H];     // rowpb for 8 local n
    __shared__ float ccm[2][32][H];    // col for 32 local m
    int tid = threadIdx.x;
    int mb = blockIdx.x * 32, nb = blockIdx.y * 8;

    if (tid < 16)  wa[tid >> 3][tid & 7]   = W1[(tid >> 3) * (H * 129) + (tid & 7) * 129];
    if (tid < 128) W2s[tid >> 6][tid & 63] = W2[tid];
    if (tid < 16)  b2s[tid >> 3][tid & 7]  = b2[tid];
    if (tid < 16)  W3s[tid >> 3][tid & 7]  = W3[tid];
    if (tid < 2)   b3s[tid] = b3[tid];
    if (tid < 128) {
        int s = tid >> 6, r = (tid >> 3) & 7, h = tid & 7;
        rcn[s][r][h] = g_rowpb[s][nb + r][h];
    }
    for (int i = tid; i < 512; i += 256) {
        int s = i >> 8, mm = (i >> 3) & 31, h = i & 7;
        ccm[s][mm][h] = g_col[s][mb + mm][h];
    }
    __syncthreads();

    int mloc = tid & 31, nloc = tid >> 5;
    int n = nb + nloc, m = mb + mloc;
    float av  = adj[n * N + m];
    float adv = adjd[n * N + m];

    {
        float rc[H];
#pragma unroll
        for (int h = 0; h < H; h++) rc[h] = rcn[0][nloc][h] + ccm[0][mloc][h];
        g_a[n * N + m] = mlp_eval(av, wa[0], rc, W2s[0], b2s[0], W3s[0], b3s[0]);
    }
    {
        float rc[H];
#pragma unroll
        for (int h = 0; h < H; h++) rc[h] = rcn[1][nloc][h] + ccm[1][mloc][h];
        g_ad[n * N + m] = mlp_eval(adv, wa[1], rc, W2s[1], b2s[1], W3s[1], b3s[1]);
    }
}

// ---------------- U_q = x @ W[l][q]  (register-tiled outer product) ----------------
// Block: 32 rows x 64 cols, one q. Thread tile: 2 rows x 4 cols.
// Per k-step: 1 LDS.128 (W row) + 1 LDS.64 (x^T) -> 8 FMA.
__global__ void __launch_bounds__(256) uproj_kernel(const float* __restrict__ y,
                                                    const float* __restrict__ gnn_W, int layer) {
    __shared__ float Ws[64 * 68];   // [k][d] padded
    __shared__ float xT[64 * 34];   // [k][row] padded (34 keeps float2 aligned)
    int tid = threadIdx.x;
    int q = blockIdx.y;
    int m0 = blockIdx.x * 32;
    const float* x = (layer == 0) ? y : g_xbuf[layer - 1];
    const float* W = gnn_W + (layer * 5 + q) * 4096;

    for (int i = tid; i < 4096; i += 256)
        Ws[(i >> 6) * 68 + (i & 63)] = W[i];
    for (int i = tid; i < 2048; i += 256) {
        int r = i >> 6, k = i & 63;
        xT[k * 34 + r] = x[(m0 + r) * D + k];
    }
    __syncthreads();

    int tc = tid & 15;     // col group: cols tc*4 .. tc*4+3
    int tr = tid >> 4;     // row group: rows tr*2 .. tr*2+1

    float acc[2][4] = {{0, 0, 0, 0}, {0, 0, 0, 0}};
#pragma unroll 16
    for (int k = 0; k < 64; k++) {
        float4 wv = *(const float4*)(Ws + k * 68 + tc * 4);
        float2 xv = *(const float2*)(xT + k * 34 + tr * 2);
        acc[0][0] = fmaf(xv.x, wv.x, acc[0][0]);
        acc[0][1] = fmaf(xv.x, wv.y, acc[0][1]);
        acc[0][2] = fmaf(xv.x, wv.z, acc[0][2]);
        acc[0][3] = fmaf(xv.x, wv.w, acc[0][3]);
        acc[1][0] = fmaf(xv.y, wv.x, acc[1][0]);
        acc[1][1] = fmaf(xv.y, wv.y, acc[1][1]);
        acc[1][2] = fmaf(xv.y, wv.z, acc[1][2]);
        acc[1][3] = fmaf(xv.y, wv.w, acc[1][3]);
    }
#pragma unroll
    for (int i = 0; i < 2; i++) {
        float4 v = make_float4(acc[i][0], acc[i][1], acc[i][2], acc[i][3]);
        *(float4*)(g_u[q] + (m0 + tr * 2 + i) * D + tc * 4) = v;
    }
}

// ---------------- fused 4-way product (split-K partials) ----------------
__global__ void __launch_bounds__(256, 2) spmm_kernel() {
    extern __shared__ float sm[];
    float* a_ds = sm;                    // [KC][PADN]  a[n,m] stored [m][n]
    float* a_ts = a_ds + KC * PADN;      // [KC][PADN]  a[m,n] stored [m][n]
    float* d_ds = a_ts + KC * PADN;
    float* d_ts = d_ds + KC * PADN;
    float* u0s  = d_ts + KC * PADN;      // [KC][PADU]
    float* u1s  = u0s + KC * PADU;
    float* u2s  = u1s + KC * PADU;
    float* u3s  = u2s + KC * PADU;

    int tid = threadIdx.x;
    int n0 = blockIdx.x * NT;
    int m0 = blockIdx.y * KC;

    // direct tiles: read a[(n0+i), m0+j] coalesced along j, store transposed
    for (int idx = tid; idx < NT * KC; idx += 256) {
        int i = idx >> 5, j = idx & 31;
        a_ds[j * PADN + i] = g_a[(n0 + i) * N + m0 + j];
        d_ds[j * PADN + i] = g_ad[(n0 + i) * N + m0 + j];
    }
    // transposed-use tiles: read a[(m0+j), n0+i] coalesced along i, store direct
    for (int idx = tid; idx < NT * KC; idx += 256) {
        int j = idx >> 7, i = idx & 127;
        a_ts[j * PADN + i] = g_a[(m0 + j) * N + n0 + i];
        d_ts[j * PADN + i] = g_ad[(m0 + j) * N + n0 + i];
    }
    for (int idx = tid; idx < KC * D; idx += 256) {
        int j = idx >> 6, d = idx & 63;
        u0s[j * PADU + d] = g_u[0][(m0 + j) * D + d];
        u1s[j * PADU + d] = g_u[1][(m0 + j) * D + d];
        u2s[j * PADU + d] = g_u[2][(m0 + j) * D + d];
        u3s[j * PADU + d] = g_u[3][(m0 + j) * D + d];
    }
    __syncthreads();

    int td = tid & 15, tn = tid >> 4;
    int dd = td * 4, nn = tn * 8;

    float acc[8][4];
#pragma unroll
    for (int i = 0; i < 8; i++)
#pragma unroll
        for (int c = 0; c < 4; c++) acc[i][c] = 0.f;

#pragma unroll 2
    for (int j = 0; j < KC; j++) {
        float4 u0 = *(const float4*)(u0s + j * PADU + dd);
        float4 u1 = *(const float4*)(u1s + j * PADU + dd);
        float4 u2 = *(const float4*)(u2s + j * PADU + dd);
        float4 u3 = *(const float4*)(u3s + j * PADU + dd);
        float aD[8], aT[8], bD[8], bT[8];
        *(float4*)(aD)     = *(const float4*)(a_ds + j * PADN + nn);
        *(float4*)(aD + 4) = *(const float4*)(a_ds + j * PADN + nn + 4);
        *(float4*)(aT)     = *(const float4*)(a_ts + j * PADN + nn);
        *(float4*)(aT + 4) = *(const float4*)(a_ts + j * PADN + nn + 4);
        *(float4*)(bD)     = *(const float4*)(d_ds + j * PADN + nn);
        *(float4*)(bD + 4) = *(const float4*)(d_ds + j * PADN + nn + 4);
        *(float4*)(bT)     = *(const float4*)(d_ts + j * PADN + nn);
        *(float4*)(bT + 4) = *(const float4*)(d_ts + j * PADN + nn + 4);
#pragma unroll
        for (int i = 0; i < 8; i++) {
            acc[i][0] = fmaf(aD[i], u0.x, fmaf(aT[i], u1.x, fmaf(bD[i], u2.x, fmaf(bT[i], u3.x, acc[i][0]))));
            acc[i][1] = fmaf(aD[i], u0.y, fmaf(aT[i], u1.y, fmaf(bD[i], u2.y, fmaf(bT[i], u3.y, acc[i][1]))));
            acc[i][2] = fmaf(aD[i], u0.z, fmaf(aT[i], u1.z, fmaf(bD[i], u2.z, fmaf(bT[i], u3.z, acc[i][2]))));
            acc[i][3] = fmaf(aD[i], u0.w, fmaf(aT[i], u1.w, fmaf(bD[i], u2.w, fmaf(bT[i], u3.w, acc[i][3]))));
        }
    }

    float* outp = g_part[blockIdx.y];
#pragma unroll
    for (int i = 0; i < 8; i++) {
        float4 v = make_float4(acc[i][0], acc[i][1], acc[i][2], acc[i][3]);
        *(float4*)(outp + (n0 + nn + i) * D + dd) = v;
    }
}

// ---------------- reduce split-K + bias (+relu) ----------------
__global__ void reduce_kernel(const float* __restrict__ gnn_b, int layer) {
    int id = blockIdx.x * 256 + threadIdx.x;   // N*D
    int d = id & 63;
    float acc = g_u[4][id] + gnn_b[layer * D + d];
#pragma unroll
    for (int s = 0; s < NSPLIT; s++) acc += g_part[s][id];
    g_xbuf[layer][id] = fmaxf(acc, 0.f);
}

// ---------------- final layer: no relu, scale by tg ----------------
__global__ void final_kernel(float* __restrict__ out, const float* __restrict__ gnn_b) {
    int id = blockIdx.x * 256 + threadIdx.x;
    int d = id & 63;
    int n = id >> 6;
    float acc = g_u[4][id] + gnn_b[2 * D + d];
#pragma unroll
    for (int s = 0; s < NSPLIT; s++) acc += g_part[s][id];
    float tg = 0.f;
#pragma unroll
    for (int s = 0; s < TG_SPLIT; s++) tg += g_tgp[s][n];
    out[id] = acc * tg * (1.0f / N);
}

// ---------------- launch ----------------
extern "C" void kernel_launch(void* const* d_in, const int* in_sizes, int n_in,
                              void* d_out, int out_size) {
    const float* y       = (const float*)d_in[0];
    const float* adj     = (const float*)d_in[1];
    const float* adjd    = (const float*)d_in[2];
    const float* t_grad  = (const float*)d_in[3];
    const float* idx_emb = (const float*)d_in[4];
    const float* msg_W1  = (const float*)d_in[5];
    const float* msg_b1  = (const float*)d_in[6];
    const float* msg_W2  = (const float*)d_in[7];
    const float* msg_b2  = (const float*)d_in[8];
    const float* msg_W3  = (const float*)d_in[9];
    const float* msg_b3  = (const float*)d_in[10];
    const float* gnn_W   = (const float*)d_in[11];
    const float* gnn_b   = (const float*)d_in[12];
    float* out = (float*)d_out;

    const int spmm_smem = (4 * KC * PADN + 4 * KC * PADU) * (int)sizeof(float); // 102400
    cudaFuncSetAttribute(spmm_kernel, cudaFuncAttributeMaxDynamicSharedMemorySize, spmm_smem);

    proj_kernel<<<128, 256>>>(idx_emb, msg_W1, msg_b1);
    tg_kernel<<<dim3(4, TG_SPLIT), 256>>>(t_grad);
    msg_kernel<<<dim3(32, 128), 256>>>(adj, adjd, msg_W1, msg_W2, msg_b2, msg_W3, msg_b3);

    for (int l = 0; l < 3; l++) {
        uproj_kernel<<<dim3(32, 5), 256>>>(y, gnn_W, l);
        spmm_kernel<<<dim3(N / NT, NSPLIT), 256, spmm_smem>>>();
        if (l < 2) reduce_kernel<<<256, 256>>>(gnn_b, l);
        else       final_kernel<<<256, 256>>>(out, gnn_b);
    }
}

// round 3
// speedup vs baseline: 1.0334x; 1.0212x over previous
#include <cuda_runtime.h>

#define N 1024
#define D 64
#define H 8
#define IDXE 64
#define NSPLIT 32     // spmm m-splits
#define KC 32         // m-chunk per block
#define NT 256        // n-tile for spmm
#define TG_SPLIT 8
#define PADA 260
#define PADU 68

typedef unsigned long long ull;

// ---------------- f32x2 helpers ----------------
__device__ __forceinline__ ull pk2(float lo, float hi) {
    ull r; asm("mov.b64 %0, {%1,%2};" : "=l"(r) : "f"(lo), "f"(hi)); return r;
}
__device__ __forceinline__ ull dup2(float x) {
    ull r; asm("mov.b64 %0, {%1,%1};" : "=l"(r) : "f"(x)); return r;
}
__device__ __forceinline__ ull fma2(ull a, ull b, ull c) {
    ull d; asm("fma.rn.f32x2 %0, %1, %2, %3;" : "=l"(d) : "l"(a), "l"(b), "l"(c)); return d;
}
__device__ __forceinline__ ull add2(ull a, ull b) {
    ull d; asm("add.rn.f32x2 %0, %1, %2;" : "=l"(d) : "l"(a), "l"(b)); return d;
}
__device__ __forceinline__ ull relu2(ull v) {
    float lo, hi;
    asm("mov.b64 {%0,%1}, %2;" : "=f"(lo), "=f"(hi) : "l"(v));
    lo = fmaxf(lo, 0.f); hi = fmaxf(hi, 0.f);
    return pk2(lo, hi);
}
__device__ __forceinline__ void unpk2(ull v, float& lo, float& hi) {
    asm("mov.b64 {%0,%1}, %2;" : "=f"(lo), "=f"(hi) : "l"(v));
}

// ---------------- static scratch ----------------
__device__ float g_a[N * N];
__device__ float g_ad[N * N];
__device__ float g_rowpb[2][N][H];   // row-proj + b1
__device__ float g_colT[2][H][N];    // col-proj, transposed for packed loads
__device__ float g_tgp[TG_SPLIT][N];
__device__ float g_xbuf[2][N * D];
__device__ float g_u[5][N * D];
__device__ float g_part[NSPLIT][N * D];

// ---------------- projections: row/col factors of the edge MLP ----------------
__global__ void proj_kernel(const float* __restrict__ idx_emb,
                            const float* __restrict__ W1,
                            const float* __restrict__ b1) {
    int id = blockIdx.x * blockDim.x + threadIdx.x;   // 32768 threads
    int h  = id & 7;
    int s  = (id >> 3) & 1;
    int rc = (id >> 4) & 1;
    int n  = id >> 5;
    const float* w = W1 + s * (H * 129) + h * 129 + 1 + rc * IDXE;
    const float* e = idx_emb + n * IDXE;
    float acc = 0.f;
#pragma unroll 16
    for (int k = 0; k < IDXE; k++) acc = fmaf(e[k], w[k], acc);
    if (rc == 0) g_rowpb[s][n][h] = acc + b1[s * H + h];
    else         g_colT[s][h][n]  = acc;
}

// ---------------- tg partials: column means of t_grad ----------------
__global__ void tg_kernel(const float* __restrict__ t_grad) {
    int n = blockIdx.x * 256 + threadIdx.x;
    int s = blockIdx.y;
    const int R = N / TG_SPLIT;
    float acc = 0.f;
    for (int m = s * R; m < (s + 1) * R; m++) acc += t_grad[m * N + n];
    g_tgp[s][n] = acc;
}

// ---------------- edge MLPs (packed pair of edges per thread) ----------------
__device__ __forceinline__ ull mlp2(ull a2, const ull* __restrict__ wa,
                                    const ull* __restrict__ rc,
                                    const ull* __restrict__ W2,
                                    const ull* __restrict__ b2,
                                    const ull* __restrict__ W3, ull b3v) {
    ull h1[H];
#pragma unroll
    for (int h = 0; h < H; h++)
        h1[h] = relu2(fma2(a2, wa[h], rc[h]));
    ull out = b3v;
#pragma unroll
    for (int k = 0; k < H; k++) {
        ull t = b2[k];
#pragma unroll
        for (int h = 0; h < H; h++) t = fma2(W2[k * H + h], h1[h], t);
        out = fma2(W3[k], relu2(t), out);
    }
    return out;
}

__global__ void __launch_bounds__(256) msg_kernel(const float* __restrict__ adj,
                           const float* __restrict__ adjd,
                           const float* __restrict__ W1,
                           const float* __restrict__ W2,
                           const float* __restrict__ b2,
                           const float* __restrict__ W3,
                           const float* __restrict__ b3) {
    __shared__ ull wa2[2][H], W2d[2][H * H], b2d[2][H], W3d[2][H], b3d[2];
    __shared__ float rcn[2][8][H];     // rowpb for 8 local n
    __shared__ ull ccm2[2][H][32];     // packed col pairs for 32 m-pairs
    int tid = threadIdx.x;
    int mb = blockIdx.x * 64, nb = blockIdx.y * 8;

    if (tid < 16) {
        int s = tid >> 3, h = tid & 7;
        wa2[s][h] = dup2(W1[s * (H * 129) + h * 129]);
        b2d[s][h] = dup2(b2[tid]);
        W3d[s][h] = dup2(W3[tid]);
    }
    if (tid < 2) b3d[tid] = dup2(b3[tid]);
    if (tid >= 32 && tid < 160) {
        int i = tid - 32;
        W2d[i >> 6][i & 63] = dup2(W2[i]);
    }
    if (tid >= 160 && tid < 160 + 128 - 32) { } // (no-op filler)
    if (tid < 128) {
        int s = tid >> 6, r = (tid >> 3) & 7, h = tid & 7;
        rcn[s][r][h] = g_rowpb[s][nb + r][h];
    }
    for (int i = tid; i < 512; i += 256) {
        int s = i >> 8, h = (i >> 5) & 7, mp = i & 31;
        float2 c = *(const float2*)(&g_colT[s][h][mb + 2 * mp]);
        ccm2[s][h][mp] = pk2(c.x, c.y);
    }
    __syncthreads();

    int mp = tid & 31, nloc = tid >> 5;
    int m0 = mb + 2 * mp, n = nb + nloc;
    float2 av  = *(const float2*)(adj  + n * N + m0);
    float2 adv = *(const float2*)(adjd + n * N + m0);

    {
        ull rc2[H];
#pragma unroll
        for (int h = 0; h < H; h++)
            rc2[h] = add2(dup2(rcn[0][nloc][h]), ccm2[0][h][mp]);
        ull o = mlp2(pk2(av.x, av.y), wa2[0], rc2, W2d[0], b2d[0], W3d[0], b3d[0]);
        float lo, hi; unpk2(o, lo, hi);
        *(float2*)(g_a + n * N + m0) = make_float2(lo, hi);
    }
    {
        ull rc2[H];
#pragma unroll
        for (int h = 0; h < H; h++)
            rc2[h] = add2(dup2(rcn[1][nloc][h]), ccm2[1][h][mp]);
        ull o = mlp2(pk2(adv.x, adv.y), wa2[1], rc2, W2d[1], b2d[1], W3d[1], b3d[1]);
        float lo, hi; unpk2(o, lo, hi);
        *(float2*)(g_ad + n * N + m0) = make_float2(lo, hi);
    }
}

// ---------------- U_q = x @ W[l][q]  (f32x2 outer product) ----------------
__global__ void __launch_bounds__(256) uproj_kernel(const float* __restrict__ y,
                                                    const float* __restrict__ gnn_W, int layer) {
    __shared__ float Ws[64 * 68];   // [k][d] padded
    __shared__ float xT[64 * 34];   // [k][row] padded
    int tid = threadIdx.x;
    int q = blockIdx.y;
    int m0 = blockIdx.x * 32;
    const float* x = (layer == 0) ? y : g_xbuf[layer - 1];
    const float* W = gnn_W + (layer * 5 + q) * 4096;

    for (int i = tid; i < 4096; i += 256)
        Ws[(i >> 6) * 68 + (i & 63)] = W[i];
    for (int i = tid; i < 2048; i += 256) {
        int r = i >> 6, k = i & 63;
        xT[k * 34 + r] = x[(m0 + r) * D + k];
    }
    __syncthreads();

    int tc = tid & 15;     // cols tc*4 .. tc*4+3
    int tr = tid >> 4;     // rows tr*2 .. tr*2+1

    ull acc[2][2] = {{0, 0}, {0, 0}};   // bits of 0.0f pair == 0ull
#pragma unroll 16
    for (int k = 0; k < 64; k++) {
        ulonglong2 wv = *(const ulonglong2*)(Ws + k * 68 + tc * 4);
        float2 xv = *(const float2*)(xT + k * 34 + tr * 2);
        ull x0 = dup2(xv.x), x1 = dup2(xv.y);
        acc[0][0] = fma2(x0, wv.x, acc[0][0]);
        acc[0][1] = fma2(x0, wv.y, acc[0][1]);
        acc[1][0] = fma2(x1, wv.x, acc[1][0]);
        acc[1][1] = fma2(x1, wv.y, acc[1][1]);
    }
#pragma unroll
    for (int i = 0; i < 2; i++) {
        ulonglong2 v; v.x = acc[i][0]; v.y = acc[i][1];
        *(ulonglong2*)(g_u[q] + (m0 + tr * 2 + i) * D + tc * 4) = v;
    }
}

// ---------------- fused 4-way product (f32x2, 256x64 tile, 1 wave) ----------------
__global__ void __launch_bounds__(256, 1) spmm_kernel() {
    extern __shared__ float sm[];
    float* a_ds = sm;                    // [KC][PADA]  a[n,m] stored [m][n]
    float* a_ts = a_ds + KC * PADA;      // [KC][PADA]  a[m,n] stored [m][n]
    float* d_ds = a_ts + KC * PADA;
    float* d_ts = d_ds + KC * PADA;
    float* u0s  = d_ts + KC * PADA;      // [KC][PADU]
    float* u1s  = u0s + KC * PADU;
    float* u2s  = u1s + KC * PADU;
    float* u3s  = u2s + KC * PADU;

    int tid = threadIdx.x;
    int n0 = blockIdx.x * NT;
    int m0 = blockIdx.y * KC;

    // direct tiles: read a[(n0+i), m0+j] coalesced along j, store transposed
    for (int idx = tid; idx < NT * KC; idx += 256) {
        int i = idx >> 5, j = idx & 31;
        a_ds[j * PADA + i] = g_a[(n0 + i) * N + m0 + j];
        d_ds[j * PADA + i] = g_ad[(n0 + i) * N + m0 + j];
    }
    // transposed-use tiles: read a[(m0+j), n0+i] coalesced along i
    for (int idx = tid; idx < NT * KC; idx += 256) {
        int j = idx >> 8, i = idx & 255;
        a_ts[j * PADA + i] = g_a[(m0 + j) * N + n0 + i];
        d_ts[j * PADA + i] = g_ad[(m0 + j) * N + n0 + i];
    }
    for (int idx = tid; idx < KC * D; idx += 256) {
        int j = idx >> 6, d = idx & 63;
        u0s[j * PADU + d] = g_u[0][(m0 + j) * D + d];
        u1s[j * PADU + d] = g_u[1][(m0 + j) * D + d];
        u2s[j * PADU + d] = g_u[2][(m0 + j) * D + d];
        u3s[j * PADU + d] = g_u[3][(m0 + j) * D + d];
    }
    __syncthreads();

    int tr = tid >> 3;      // 0..31 -> rows i0 = tr*8
    int tc = tid & 7;       // 0..7  -> cols c0 = tc*8
    int i0 = tr * 8, c0 = tc * 8;

    ull acc[8][4];
#pragma unroll
    for (int i = 0; i < 8; i++)
#pragma unroll
        for (int c = 0; c < 4; c++) acc[i][c] = 0ull;

    for (int j = 0; j < KC; j++) {
        ulonglong2 u0p = *(const ulonglong2*)(u0s + j * PADU + c0);
        ulonglong2 u0q = *(const ulonglong2*)(u0s + j * PADU + c0 + 4);
        ulonglong2 u1p = *(const ulonglong2*)(u1s + j * PADU + c0);
        ulonglong2 u1q = *(const ulonglong2*)(u1s + j * PADU + c0 + 4);
        ulonglong2 u2p = *(const ulonglong2*)(u2s + j * PADU + c0);
        ulonglong2 u2q = *(const ulonglong2*)(u2s + j * PADU + c0 + 4);
        ulonglong2 u3p = *(const ulonglong2*)(u3s + j * PADU + c0);
        ulonglong2 u3q = *(const ulonglong2*)(u3s + j * PADU + c0 + 4);
        float aD[8], aT[8], bD[8], bT[8];
        *(float4*)(aD)     = *(const float4*)(a_ds + j * PADA + i0);
        *(float4*)(aD + 4) = *(const float4*)(a_ds + j * PADA + i0 + 4);
        *(float4*)(aT)     = *(const float4*)(a_ts + j * PADA + i0);
        *(float4*)(aT + 4) = *(const float4*)(a_ts + j * PADA + i0 + 4);
        *(float4*)(bD)     = *(const float4*)(d_ds + j * PADA + i0);
        *(float4*)(bD + 4) = *(const float4*)(d_ds + j * PADA + i0 + 4);
        *(float4*)(bT)     = *(const float4*)(d_ts + j * PADA + i0);
        *(float4*)(bT + 4) = *(const float4*)(d_ts + j * PADA + i0 + 4);
#pragma unroll
        for (int i = 0; i < 8; i++) {
            ull aDd = dup2(aD[i]), aTd = dup2(aT[i]);
            ull bDd = dup2(bD[i]), bTd = dup2(bT[i]);
            acc[i][0] = fma2(aDd, u0p.x, fma2(aTd, u1p.x, fma2(bDd, u2p.x, fma2(bTd, u3p.x, acc[i][0]))));
            acc[i][1] = fma2(aDd, u0p.y, fma2(aTd, u1p.y, fma2(bDd, u2p.y, fma2(bTd, u3p.y, acc[i][1]))));
            acc[i][2] = fma2(aDd, u0q.x, fma2(aTd, u1q.x, fma2(bDd, u2q.x, fma2(bTd, u3q.x, acc[i][2]))));
            acc[i][3] = fma2(aDd, u0q.y, fma2(aTd, u1q.y, fma2(bDd, u2q.y, fma2(bTd, u3q.y, acc[i][3]))));
        }
    }

    float* outp = g_part[blockIdx.y];
#pragma unroll
    for (int i = 0; i < 8; i++) {
        ulonglong2 v0; v0.x = acc[i][0]; v0.y = acc[i][1];
        ulonglong2 v1; v1.x = acc[i][2]; v1.y = acc[i][3];
        *(ulonglong2*)(outp + (n0 + i0 + i) * D + c0)     = v0;
        *(ulonglong2*)(outp + (n0 + i0 + i) * D + c0 + 4) = v1;
    }
}

// ---------------- reduce split-K + bias (+relu), float4 ----------------
__global__ void reduce_kernel(const float* __restrict__ gnn_b, int layer) {
    int id = blockIdx.x * 256 + threadIdx.x;    // over N*D/4
    const float4* u4 = (const float4*)g_u[4];
    float4 acc = u4[id];
    float4 b = ((const float4*)(gnn_b + layer * D))[id & 15];
    acc.x += b.x; acc.y += b.y; acc.z += b.z; acc.w += b.w;
#pragma unroll
    for (int s = 0; s < NSPLIT; s++) {
        float4 p = ((const float4*)g_part[s])[id];
        acc.x += p.x; acc.y += p.y; acc.z += p.z; acc.w += p.w;
    }
    acc.x = fmaxf(acc.x, 0.f); acc.y = fmaxf(acc.y, 0.f);
    acc.z = fmaxf(acc.z, 0.f); acc.w = fmaxf(acc.w, 0.f);
    ((float4*)g_xbuf[layer])[id] = acc;
}

// ---------------- final layer: no relu, scale by tg ----------------
__global__ void final_kernel(float* __restrict__ out, const float* __restrict__ gnn_b) {
    int id = blockIdx.x * 256 + threadIdx.x;    // over N*D/4
    const float4* u4 = (const float4*)g_u[4];
    float4 acc = u4[id];
    float4 b = ((const float4*)(gnn_b + 2 * D))[id & 15];
    acc.x += b.x; acc.y += b.y; acc.z += b.z; acc.w += b.w;
#pragma unroll
    for (int s = 0; s < NSPLIT; s++) {
        float4 p = ((const float4*)g_part[s])[id];
        acc.x += p.x; acc.y += p.y; acc.z += p.z; acc.w += p.w;
    }
    int n = id >> 4;
    float tg = 0.f;
#pragma unroll
    for (int s = 0; s < TG_SPLIT; s++) tg += g_tgp[s][n];
    tg *= (1.0f / N);
    float4 r = make_float4(acc.x * tg, acc.y * tg, acc.z * tg, acc.w * tg);
    ((float4*)out)[id] = r;
}

// ---------------- launch ----------------
extern "C" void kernel_launch(void* const* d_in, const int* in_sizes, int n_in,
                              void* d_out, int out_size) {
    const float* y       = (const float*)d_in[0];
    const float* adj     = (const float*)d_in[1];
    const float* adjd    = (const float*)d_in[2];
    const float* t_grad  = (const float*)d_in[3];
    const float* idx_emb = (const float*)d_in[4];
    const float* msg_W1  = (const float*)d_in[5];
    const float* msg_b1  = (const float*)d_in[6];
    const float* msg_W2  = (const float*)d_in[7];
    const float* msg_b2  = (const float*)d_in[8];
    const float* msg_W3  = (const float*)d_in[9];
    const float* msg_b3  = (const float*)d_in[10];
    const float* gnn_W   = (const float*)d_in[11];
    const float* gnn_b   = (const float*)d_in[12];
    float* out = (float*)d_out;

    const int spmm_smem = (4 * KC * PADA + 4 * KC * PADU) * (int)sizeof(float); // 167936
    cudaFuncSetAttribute(spmm_kernel, cudaFuncAttributeMaxDynamicSharedMemorySize, spmm_smem);

    proj_kernel<<<128, 256>>>(idx_emb, msg_W1, msg_b1);
    tg_kernel<<<dim3(4, TG_SPLIT), 256>>>(t_grad);
    msg_kernel<<<dim3(16, 128), 256>>>(adj, adjd, msg_W1, msg_W2, msg_b2, msg_W3, msg_b3);

    for (int l = 0; l < 3; l++) {
        uproj_kernel<<<dim3(32, 5), 256>>>(y, gnn_W, l);
        spmm_kernel<<<dim3(N / NT, NSPLIT), 256, spmm_smem>>>();
        if (l < 2) reduce_kernel<<<64, 256>>>(gnn_b, l);
        else       final_kernel<<<64, 256>>>(out, gnn_b);
    }
}